// round 1
// baseline (speedup 1.0000x reference)
#include <cuda_runtime.h>

#define NTOT (16*64*256*256)
#define CHW  (64*256*256)
#define HW   (256*256)

// Scratch + scalar state (static __device__ allocation — no cudaMalloc).
__device__ float g_buf1[NTOT];
__device__ float g_buf2[NTOT];
__device__ unsigned g_maxX, g_maxY1, g_maxY3, g_maxY4;   // float bits of max|.|, >= 0
__device__ float g_swp1, g_swf1, g_swp2, g_swf2;          // weight scales
__device__ unsigned g_wp1[1024];   // packed int8 weights [co][k] (k = ci/4)
__device__ unsigned g_wp2[1024];
__device__ int g_wf1[576];         // depthwise int weights [c][9]
__device__ int g_wf2[576];

// ---------------- prep: zero maxes, quantize all weights (1 block) ----------
__global__ void k_prep(const float* __restrict__ wp1, const float* __restrict__ wf1,
                       const float* __restrict__ wp2, const float* __restrict__ wf2) {
    __shared__ float red[256];
    int tid = threadIdx.x;
    if (tid == 0) { g_maxX = 0u; g_maxY1 = 0u; g_maxY3 = 0u; g_maxY4 = 0u; }

    // ---- w_p1 ----
    float m = 0.f;
    for (int i = tid; i < 4096; i += 256) m = fmaxf(m, fabsf(wp1[i]));
    red[tid] = m; __syncthreads();
    for (int s = 128; s > 0; s >>= 1) { if (tid < s) red[tid] = fmaxf(red[tid], red[tid+s]); __syncthreads(); }
    float s1 = red[0] / 7.0f + 1e-12f;
    __syncthreads();
    for (int i = tid; i < 1024; i += 256) {
        int co = i >> 4, k = i & 15;
        unsigned pk = 0;
        for (int j = 0; j < 4; j++) {
            float w = wp1[co*64 + k*4 + j];
            int q = __float2int_rn(__fdiv_rn(w, s1));
            q = max(-7, min(7, q));
            pk |= (unsigned)(q & 255) << (8*j);
        }
        g_wp1[i] = pk;
    }
    if (tid == 0) g_swp1 = s1;

    // ---- w_f1 ----
    m = 0.f;
    for (int i = tid; i < 576; i += 256) m = fmaxf(m, fabsf(wf1[i]));
    red[tid] = m; __syncthreads();
    for (int s = 128; s > 0; s >>= 1) { if (tid < s) red[tid] = fmaxf(red[tid], red[tid+s]); __syncthreads(); }
    float s2 = red[0] / 7.0f + 1e-12f;
    __syncthreads();
    for (int i = tid; i < 576; i += 256) {
        int q = __float2int_rn(__fdiv_rn(wf1[i], s2));
        g_wf1[i] = max(-7, min(7, q));
    }
    if (tid == 0) g_swf1 = s2;

    // ---- w_p2 ----
    m = 0.f;
    for (int i = tid; i < 4096; i += 256) m = fmaxf(m, fabsf(wp2[i]));
    red[tid] = m; __syncthreads();
    for (int s = 128; s > 0; s >>= 1) { if (tid < s) red[tid] = fmaxf(red[tid], red[tid+s]); __syncthreads(); }
    float s3 = red[0] / 7.0f + 1e-12f;
    __syncthreads();
    for (int i = tid; i < 1024; i += 256) {
        int co = i >> 4, k = i & 15;
        unsigned pk = 0;
        for (int j = 0; j < 4; j++) {
            float w = wp2[co*64 + k*4 + j];
            int q = __float2int_rn(__fdiv_rn(w, s3));
            q = max(-7, min(7, q));
            pk |= (unsigned)(q & 255) << (8*j);
        }
        g_wp2[i] = pk;
    }
    if (tid == 0) g_swp2 = s3;

    // ---- w_f2 ----
    m = 0.f;
    for (int i = tid; i < 576; i += 256) m = fmaxf(m, fabsf(wf2[i]));
    red[tid] = m; __syncthreads();
    for (int s = 128; s > 0; s >>= 1) { if (tid < s) red[tid] = fmaxf(red[tid], red[tid+s]); __syncthreads(); }
    float s4 = red[0] / 7.0f + 1e-12f;
    __syncthreads();
    for (int i = tid; i < 576; i += 256) {
        int q = __float2int_rn(__fdiv_rn(wf2[i], s4));
        g_wf2[i] = max(-7, min(7, q));
    }
    if (tid == 0) g_swf2 = s4;
}

// ---------------- global max|x| ----------------
__global__ void k_maxabs(const float4* __restrict__ x) {
    float m = 0.f;
    int stride = gridDim.x * blockDim.x;
    for (int i = blockIdx.x * blockDim.x + threadIdx.x; i < NTOT/4; i += stride) {
        float4 v = x[i];
        m = fmaxf(m, fmaxf(fmaxf(fabsf(v.x), fabsf(v.y)), fmaxf(fabsf(v.z), fabsf(v.w))));
    }
    #pragma unroll
    for (int o = 16; o; o >>= 1) m = fmaxf(m, __shfl_xor_sync(0xffffffffu, m, o));
    if ((threadIdx.x & 31) == 0) atomicMax(&g_maxX, __float_as_uint(m));
}

// ---------------- 1x1 conv (quant in, dp4a GEMM, fused max of out) ----------
// which==0: in = x (ext),    w = wp1, maxin = g_maxX,  out = g_buf1, maxout = g_maxY1
// which==1: in = g_buf2,     w = wp2, maxin = g_maxY3, out = g_buf1, maxout = g_maxY4
__global__ void __launch_bounds__(256, 2) k_pw(int which, const float* __restrict__ xext) {
    __shared__ __align__(16) unsigned xs[16][256];
    __shared__ __align__(16) unsigned ws[16][64];

    const float* in = which ? (const float*)g_buf2 : xext;
    const unsigned* wq = which ? g_wp2 : g_wp1;
    float maxin = __uint_as_float(which ? g_maxY3 : g_maxX);
    float sw = which ? g_swp2 : g_swp1;
    float s_in = maxin / 127.0f + 1e-12f;
    float inv = 1.0f / s_in;

    int tid = threadIdx.x;
    int n = blockIdx.y;
    int px0 = blockIdx.x << 8;
    const float* xb = in + (size_t)n * CHW + px0 + tid;

    // load 256 px x 64 ci, quantize to int8, pack 4 ci per u32
    #pragma unroll
    for (int k = 0; k < 16; k++) {
        unsigned pk = 0;
        #pragma unroll
        for (int j = 0; j < 4; j++) {
            float v = xb[(size_t)(4*k + j) * HW];
            int q = __float2int_rn(v * inv);
            q = max(-127, min(127, q));
            pk |= (unsigned)(q & 255) << (8*j);
        }
        xs[k][tid] = pk;
    }
    for (int i = tid; i < 1024; i += 256) ws[i & 15][i >> 4] = wq[i];
    __syncthreads();

    int cg = tid >> 5, pg = tid & 31;
    int co0 = cg << 3, p0 = pg << 3;

    int acc[8][8];
    #pragma unroll
    for (int c = 0; c < 8; c++)
        #pragma unroll
        for (int p = 0; p < 8; p++) acc[c][p] = 0;

    #pragma unroll
    for (int k = 0; k < 16; k++) {
        uint4 x0 = *(const uint4*)&xs[k][p0];
        uint4 x1 = *(const uint4*)&xs[k][p0 + 4];
        uint4 w0 = *(const uint4*)&ws[k][co0];
        uint4 w1 = *(const uint4*)&ws[k][co0 + 4];
        int xv[8] = {(int)x0.x,(int)x0.y,(int)x0.z,(int)x0.w,(int)x1.x,(int)x1.y,(int)x1.z,(int)x1.w};
        int wv[8] = {(int)w0.x,(int)w0.y,(int)w0.z,(int)w0.w,(int)w1.x,(int)w1.y,(int)w1.z,(int)w1.w};
        #pragma unroll
        for (int c = 0; c < 8; c++)
            #pragma unroll
            for (int p = 0; p < 8; p++)
                acc[c][p] = __dp4a(wv[c], xv[p], acc[c][p]);
    }

    float cmul = s_in * sw;
    float lmax = 0.f;
    float* out = g_buf1 + (size_t)n * CHW + px0 + p0;
    #pragma unroll
    for (int c = 0; c < 8; c++) {
        float v[8];
        #pragma unroll
        for (int p = 0; p < 8; p++) {
            v[p] = (float)acc[c][p] * cmul;
            lmax = fmaxf(lmax, fabsf(v[p]));
        }
        float4* op = (float4*)(out + (size_t)(co0 + c) * HW);
        op[0] = make_float4(v[0], v[1], v[2], v[3]);
        op[1] = make_float4(v[4], v[5], v[6], v[7]);
    }
    #pragma unroll
    for (int o = 16; o; o >>= 1) lmax = fmaxf(lmax, __shfl_xor_sync(0xffffffffu, lmax, o));
    if ((tid & 31) == 0) atomicMax(which ? &g_maxY4 : &g_maxY1, __float_as_uint(lmax));
}

// ---------------- depthwise 3x3 + prelu (+residual) -------------------------
// which==0: in g_buf1 (maxin g_maxY1, w f1, alpha1) -> g_buf2, track g_maxY3
// which==1: in g_buf1 (maxin g_maxY4, w f2, alpha2) -> +x -> d_out, no tracking
__global__ void __launch_bounds__(256) k_dw(int which, const float* __restrict__ alpha,
                                            const float* __restrict__ residual,
                                            float* __restrict__ dout) {
    __shared__ int xs[34][36];
    int tid = threadIdx.x;
    int c = blockIdx.y, n = blockIdx.z;
    int th0 = (blockIdx.x >> 3) << 5, tw0 = (blockIdx.x & 7) << 5;
    size_t poff = ((size_t)n * 64 + c) * HW;
    const float* plane = g_buf1 + poff;

    float maxin = __uint_as_float(which ? g_maxY4 : g_maxY1);
    float sw = which ? g_swf2 : g_swf1;
    const int* wq = (which ? g_wf2 : g_wf1) + c * 9;
    float s_in = maxin / 127.0f + 1e-12f;
    float inv = 1.0f / s_in;

    for (int i = tid; i < 34 * 34; i += 256) {
        int r = i / 34, col = i - r * 34;
        int gr = th0 + r - 1, gc = tw0 + col - 1;
        int v = 0;
        if (gr >= 0 && gr < 256 && gc >= 0 && gc < 256) {
            float f = plane[gr * 256 + gc];
            int q = __float2int_rn(f * inv);
            v = max(-127, min(127, q));
        }
        xs[r][col] = v;
    }
    int w[9];
    #pragma unroll
    for (int i = 0; i < 9; i++) w[i] = wq[i];
    float al = alpha[c];
    float cmul = s_in * sw;
    __syncthreads();

    int ty = tid >> 4, tx = tid & 15;
    int r0 = ty << 1, c0 = tx << 1;
    int m[4][4];
    #pragma unroll
    for (int i = 0; i < 4; i++)
        #pragma unroll
        for (int j = 0; j < 4; j++) m[i][j] = xs[r0 + i][c0 + j];

    float* obase = which ? dout : g_buf2;
    float* oplane = obase + poff;
    float lmax = 0.f;
    #pragma unroll
    for (int dy = 0; dy < 2; dy++) {
        #pragma unroll
        for (int dx = 0; dx < 2; dx++) {
            int acc = 0;
            #pragma unroll
            for (int kh = 0; kh < 3; kh++)
                #pragma unroll
                for (int kw = 0; kw < 3; kw++)
                    acc += m[dy + kh][dx + kw] * w[kh * 3 + kw];
            float f = (float)acc * cmul;
            f = f > 0.f ? f : al * f;
            int gr = th0 + r0 + dy, gc = tw0 + c0 + dx;
            if (which) f += residual[poff + gr * 256 + gc];
            else       lmax = fmaxf(lmax, fabsf(f));
            oplane[gr * 256 + gc] = f;
        }
    }
    if (!which) {
        #pragma unroll
        for (int o = 16; o; o >>= 1) lmax = fmaxf(lmax, __shfl_xor_sync(0xffffffffu, lmax, o));
        if ((tid & 31) == 0) atomicMax(&g_maxY3, __float_as_uint(lmax));
    }
}

extern "C" void kernel_launch(void* const* d_in, const int* in_sizes, int n_in,
                              void* d_out, int out_size) {
    const float* x   = (const float*)d_in[0];
    const float* wp1 = (const float*)d_in[1];
    const float* wf1 = (const float*)d_in[2];
    const float* wp2 = (const float*)d_in[3];
    const float* wf2 = (const float*)d_in[4];
    const float* a1  = (const float*)d_in[5];
    const float* a2  = (const float*)d_in[6];
    float* out = (float*)d_out;

    k_prep<<<1, 256>>>(wp1, wf1, wp2, wf2);
    k_maxabs<<<2048, 256>>>((const float4*)x);
    k_pw<<<dim3(256, 16), 256>>>(0, x);                 // x  -> buf1 (y1), maxY1
    k_dw<<<dim3(64, 64, 16), 256>>>(0, a1, nullptr, nullptr); // buf1 -> buf2 (y3), maxY3
    k_pw<<<dim3(256, 16), 256>>>(1, nullptr);           // buf2 -> buf1 (y4), maxY4
    k_dw<<<dim3(64, 64, 16), 256>>>(1, a2, x, out);     // buf1 -> out (+x)
}

// round 2
// speedup vs baseline: 1.7794x; 1.7794x over previous
#include <cuda_runtime.h>

#define NTOT (16*64*256*256)
#define CHW  (64*256*256)
#define HW   (256*256)

// Scratch + scalar state (static __device__ allocation — no cudaMalloc).
__device__ float g_buf1[NTOT];
__device__ float g_buf2[NTOT];
__device__ unsigned g_maxX, g_maxY1, g_maxY3, g_maxY4;   // float bits of max|.|, >= 0
__device__ float g_swp1, g_swf1, g_swp2, g_swf2;          // weight scales
__device__ unsigned g_wp1[1024];   // packed int8 weights [co][k] (k = ci/4)
__device__ unsigned g_wp2[1024];
__device__ int g_wf1[576];         // depthwise int weights [c][9]
__device__ int g_wf2[576];

// ---------------- prep: zero maxes, quantize all weights (1 block) ----------
__global__ void k_prep(const float* __restrict__ wp1, const float* __restrict__ wf1,
                       const float* __restrict__ wp2, const float* __restrict__ wf2) {
    __shared__ float red[256];
    int tid = threadIdx.x;
    if (tid == 0) { g_maxX = 0u; g_maxY1 = 0u; g_maxY3 = 0u; g_maxY4 = 0u; }

    // ---- w_p1 ----
    float m = 0.f;
    for (int i = tid; i < 4096; i += 256) m = fmaxf(m, fabsf(wp1[i]));
    red[tid] = m; __syncthreads();
    for (int s = 128; s > 0; s >>= 1) { if (tid < s) red[tid] = fmaxf(red[tid], red[tid+s]); __syncthreads(); }
    float s1 = red[0] / 7.0f + 1e-12f;
    __syncthreads();
    for (int i = tid; i < 1024; i += 256) {
        int co = i >> 4, k = i & 15;
        unsigned pk = 0;
        for (int j = 0; j < 4; j++) {
            float w = wp1[co*64 + k*4 + j];
            int q = __float2int_rn(__fdiv_rn(w, s1));
            q = max(-7, min(7, q));
            pk |= (unsigned)(q & 255) << (8*j);
        }
        g_wp1[i] = pk;
    }
    if (tid == 0) g_swp1 = s1;

    // ---- w_f1 ----
    m = 0.f;
    for (int i = tid; i < 576; i += 256) m = fmaxf(m, fabsf(wf1[i]));
    red[tid] = m; __syncthreads();
    for (int s = 128; s > 0; s >>= 1) { if (tid < s) red[tid] = fmaxf(red[tid], red[tid+s]); __syncthreads(); }
    float s2 = red[0] / 7.0f + 1e-12f;
    __syncthreads();
    for (int i = tid; i < 576; i += 256) {
        int q = __float2int_rn(__fdiv_rn(wf1[i], s2));
        g_wf1[i] = max(-7, min(7, q));
    }
    if (tid == 0) g_swf1 = s2;

    // ---- w_p2 ----
    m = 0.f;
    for (int i = tid; i < 4096; i += 256) m = fmaxf(m, fabsf(wp2[i]));
    red[tid] = m; __syncthreads();
    for (int s = 128; s > 0; s >>= 1) { if (tid < s) red[tid] = fmaxf(red[tid], red[tid+s]); __syncthreads(); }
    float s3 = red[0] / 7.0f + 1e-12f;
    __syncthreads();
    for (int i = tid; i < 1024; i += 256) {
        int co = i >> 4, k = i & 15;
        unsigned pk = 0;
        for (int j = 0; j < 4; j++) {
            float w = wp2[co*64 + k*4 + j];
            int q = __float2int_rn(__fdiv_rn(w, s3));
            q = max(-7, min(7, q));
            pk |= (unsigned)(q & 255) << (8*j);
        }
        g_wp2[i] = pk;
    }
    if (tid == 0) g_swp2 = s3;

    // ---- w_f2 ----
    m = 0.f;
    for (int i = tid; i < 576; i += 256) m = fmaxf(m, fabsf(wf2[i]));
    red[tid] = m; __syncthreads();
    for (int s = 128; s > 0; s >>= 1) { if (tid < s) red[tid] = fmaxf(red[tid], red[tid+s]); __syncthreads(); }
    float s4 = red[0] / 7.0f + 1e-12f;
    __syncthreads();
    for (int i = tid; i < 576; i += 256) {
        int q = __float2int_rn(__fdiv_rn(wf2[i], s4));
        g_wf2[i] = max(-7, min(7, q));
    }
    if (tid == 0) g_swf2 = s4;
}

// ---------------- global max|x| ----------------
__global__ void k_maxabs(const float4* __restrict__ x) {
    float m = 0.f;
    int stride = gridDim.x * blockDim.x;
    for (int i = blockIdx.x * blockDim.x + threadIdx.x; i < NTOT/4; i += stride) {
        float4 v = x[i];
        m = fmaxf(m, fmaxf(fmaxf(fabsf(v.x), fabsf(v.y)), fmaxf(fabsf(v.z), fabsf(v.w))));
    }
    #pragma unroll
    for (int o = 16; o; o >>= 1) m = fmaxf(m, __shfl_xor_sync(0xffffffffu, m, o));
    if ((threadIdx.x & 31) == 0) atomicMax(&g_maxX, __float_as_uint(m));
}

// ---------------- 1x1 conv (quant in, dp4a GEMM, fused max of out) ----------
// which==0: in = x (ext),    w = wp1, maxin = g_maxX,  out = g_buf1, maxout = g_maxY1
// which==1: in = g_buf2,     w = wp2, maxin = g_maxY3, out = g_buf1, maxout = g_maxY4
__global__ void __launch_bounds__(256, 2) k_pw(int which, const float* __restrict__ xext) {
    __shared__ __align__(16) unsigned xs[16][256];
    __shared__ __align__(16) unsigned ws[16][64];

    const float* in = which ? (const float*)g_buf2 : xext;
    const unsigned* wq = which ? g_wp2 : g_wp1;
    float maxin = __uint_as_float(which ? g_maxY3 : g_maxX);
    float sw = which ? g_swp2 : g_swp1;
    float s_in = maxin / 127.0f + 1e-12f;
    float inv = 1.0f / s_in;

    int tid = threadIdx.x;
    int n = blockIdx.y;
    int px0 = blockIdx.x << 8;
    const float* xb = in + (size_t)n * CHW + px0 + tid;

    // load 256 px x 64 ci, quantize to int8, pack 4 ci per u32
    #pragma unroll
    for (int k = 0; k < 16; k++) {
        unsigned pk = 0;
        #pragma unroll
        for (int j = 0; j < 4; j++) {
            float v = xb[(size_t)(4*k + j) * HW];
            int q = __float2int_rn(v * inv);
            q = max(-127, min(127, q));
            pk |= (unsigned)(q & 255) << (8*j);
        }
        xs[k][tid] = pk;
    }
    for (int i = tid; i < 1024; i += 256) ws[i & 15][i >> 4] = wq[i];
    __syncthreads();

    int cg = tid >> 5, pg = tid & 31;
    int co0 = cg << 3, p0 = pg << 3;

    int acc[8][8];
    #pragma unroll
    for (int c = 0; c < 8; c++)
        #pragma unroll
        for (int p = 0; p < 8; p++) acc[c][p] = 0;

    #pragma unroll
    for (int k = 0; k < 16; k++) {
        uint4 x0 = *(const uint4*)&xs[k][p0];
        uint4 x1 = *(const uint4*)&xs[k][p0 + 4];
        uint4 w0 = *(const uint4*)&ws[k][co0];
        uint4 w1 = *(const uint4*)&ws[k][co0 + 4];
        int xv[8] = {(int)x0.x,(int)x0.y,(int)x0.z,(int)x0.w,(int)x1.x,(int)x1.y,(int)x1.z,(int)x1.w};
        int wv[8] = {(int)w0.x,(int)w0.y,(int)w0.z,(int)w0.w,(int)w1.x,(int)w1.y,(int)w1.z,(int)w1.w};
        #pragma unroll
        for (int c = 0; c < 8; c++)
            #pragma unroll
            for (int p = 0; p < 8; p++)
                acc[c][p] = __dp4a(wv[c], xv[p], acc[c][p]);
    }

    float cmul = s_in * sw;
    float lmax = 0.f;
    float* out = g_buf1 + (size_t)n * CHW + px0 + p0;
    #pragma unroll
    for (int c = 0; c < 8; c++) {
        float v[8];
        #pragma unroll
        for (int p = 0; p < 8; p++) {
            v[p] = (float)acc[c][p] * cmul;
            lmax = fmaxf(lmax, fabsf(v[p]));
        }
        float4* op = (float4*)(out + (size_t)(co0 + c) * HW);
        op[0] = make_float4(v[0], v[1], v[2], v[3]);
        op[1] = make_float4(v[4], v[5], v[6], v[7]);
    }
    #pragma unroll
    for (int o = 16; o; o >>= 1) lmax = fmaxf(lmax, __shfl_xor_sync(0xffffffffu, lmax, o));
    if ((tid & 31) == 0) atomicMax(which ? &g_maxY4 : &g_maxY1, __float_as_uint(lmax));
}

// ---------------- depthwise 3x3 + prelu (+residual) -------------------------
// Strip design: block handles 256 cols x 16 rows of one (n,c) plane.
// which==0: in g_buf1 (maxin g_maxY1, w f1, alpha1) -> g_buf2, track g_maxY3
// which==1: in g_buf1 (maxin g_maxY4, w f2, alpha2) -> +x -> d_out, no tracking
__global__ void __launch_bounds__(256) k_dw(int which, const float* __restrict__ alpha,
                                            const float* __restrict__ residual,
                                            float* __restrict__ dout) {
    __shared__ int s[18][260];   // [row][1+col], cols -1 and 256 -> idx 0 and 257 (zero halo)

    int tid = threadIdx.x;
    int c = blockIdx.y, n = blockIdx.z;
    int r0 = blockIdx.x << 4;                 // strip start row
    size_t poff = ((size_t)n * 64 + c) * HW;
    const float4* plane4 = (const float4*)(g_buf1 + poff);

    float maxin = __uint_as_float(which ? g_maxY4 : g_maxY1);
    float sw = which ? g_swf2 : g_swf1;
    const int* wq = (which ? g_wf2 : g_wf1) + c * 9;
    float s_in = maxin / 127.0f + 1e-12f;
    float inv = 1.0f / s_in;

    // column halo zeros (rows 0..17, cols 0 and 257)
    if (tid < 36) s[tid >> 1][(tid & 1) ? 257 : 0] = 0;

    // load 18 rows x 64 float4, quantize once into smem ints
    #pragma unroll
    for (int it = 0; it < 5; it++) {
        int idx = tid + (it << 8);
        if (idx < 18 * 64) {
            int r = idx >> 6, f4c = idx & 63;
            int gr = r0 + r - 1;
            float4 v = make_float4(0.f, 0.f, 0.f, 0.f);
            if (gr >= 0 && gr < 256) v = plane4[gr * 64 + f4c];
            int base = 1 + (f4c << 2);
            int q0 = max(-127, min(127, __float2int_rn(v.x * inv)));
            int q1 = max(-127, min(127, __float2int_rn(v.y * inv)));
            int q2 = max(-127, min(127, __float2int_rn(v.z * inv)));
            int q3 = max(-127, min(127, __float2int_rn(v.w * inv)));
            s[r][base]     = q0;
            s[r][base + 1] = q1;
            s[r][base + 2] = q2;
            s[r][base + 3] = q3;
        }
    }

    int w[9];
    #pragma unroll
    for (int i = 0; i < 9; i++) w[i] = wq[i];
    float al = alpha[c];
    float cmul = s_in * sw;
    __syncthreads();

    // thread = one column; 16 output rows with sliding 3-row register window
    int ci = 1 + tid;
    int t0 = s[0][ci - 1], t1 = s[0][ci], t2 = s[0][ci + 1];
    int m0 = s[1][ci - 1], m1 = s[1][ci], m2 = s[1][ci + 1];

    float* obase = which ? dout : g_buf2;
    float* oplane = obase + poff;
    const float* rplane = which ? (residual + poff) : nullptr;
    float lmax = 0.f;

    #pragma unroll
    for (int r = 0; r < 16; r++) {
        int b0 = s[r + 2][ci - 1], b1 = s[r + 2][ci], b2 = s[r + 2][ci + 1];
        int acc = t0 * w[0] + t1 * w[1] + t2 * w[2]
                + m0 * w[3] + m1 * w[4] + m2 * w[5]
                + b0 * w[6] + b1 * w[7] + b2 * w[8];
        float f = (float)acc * cmul;
        f = f > 0.f ? f : al * f;
        int off = (r0 + r) * 256 + tid;
        if (which) f += rplane[off];
        else       lmax = fmaxf(lmax, fabsf(f));
        oplane[off] = f;
        t0 = m0; t1 = m1; t2 = m2;
        m0 = b0; m1 = b1; m2 = b2;
    }

    if (!which) {
        #pragma unroll
        for (int o = 16; o; o >>= 1) lmax = fmaxf(lmax, __shfl_xor_sync(0xffffffffu, lmax, o));
        if ((tid & 31) == 0) atomicMax(&g_maxY3, __float_as_uint(lmax));
    }
}

extern "C" void kernel_launch(void* const* d_in, const int* in_sizes, int n_in,
                              void* d_out, int out_size) {
    const float* x   = (const float*)d_in[0];
    const float* wp1 = (const float*)d_in[1];
    const float* wf1 = (const float*)d_in[2];
    const float* wp2 = (const float*)d_in[3];
    const float* wf2 = (const float*)d_in[4];
    const float* a1  = (const float*)d_in[5];
    const float* a2  = (const float*)d_in[6];
    float* out = (float*)d_out;

    k_prep<<<1, 256>>>(wp1, wf1, wp2, wf2);
    k_maxabs<<<2048, 256>>>((const float4*)x);
    k_pw<<<dim3(256, 16), 256>>>(0, x);                       // x    -> buf1 (y1), maxY1
    k_dw<<<dim3(16, 64, 16), 256>>>(0, a1, nullptr, nullptr); // buf1 -> buf2 (y3), maxY3
    k_pw<<<dim3(256, 16), 256>>>(1, nullptr);                 // buf2 -> buf1 (y4), maxY4
    k_dw<<<dim3(16, 64, 16), 256>>>(1, a2, x, out);           // buf1 -> out (+x)
}